// round 13
// baseline (speedup 1.0000x reference)
#include <cuda_runtime.h>
#include <cuda_fp16.h>
#include <cstdint>

// Problem constants
#define BATCH 1024
#define NN 96
#define DIM 512
#define D2 256
#define D4 128

// Scratch layout (floats; W2H region reinterpreted as half)
#define OFF_PRE 0                        // [1024][512]  img@W1_top + b1
#define OFF_T   (OFF_PRE + BATCH*DIM)    // [2][96][512] text@W1_bot
#define OFF_E   (OFF_T + 2*NN*DIM)       // [2][1024][96] exp(softmax(sims))
#define OFF_S2  (OFF_E + 2*BATCH*NN)     // [2][1024][256] sum_n relu(h1@W2+b2)
#define OFF_W2T (OFF_S2 + 2*BATCH*D2)    // half[256][512] = fp16(W2^T)
#define SCRATCH_TOTAL (OFF_W2T + DIM*D2)

__device__ float g_scratch[SCRATCH_TOTAL];

__device__ __forceinline__ uint32_t smem_u32(const void* p) {
    uint32_t a;
    asm("{ .reg .u64 t; cvta.to.shared.u64 t, %1; cvt.u32.u64 %0, t; }"
        : "=r"(a) : "l"(p));
    return a;
}
__device__ __forceinline__ uint32_t packh2(float x, float y) {
    __half2 h = __floats2half2_rn(x, y);
    return *(uint32_t*)&h;
}

#define LDSM_X4(r0, r1, r2, r3, addr) \
    asm volatile("ldmatrix.sync.aligned.m8n8.x4.shared.b16 {%0,%1,%2,%3}, [%4];" \
        : "=r"(r0), "=r"(r1), "=r"(r2), "=r"(r3) : "r"(addr))

#define MMA_F16(c, a, b0, b1) \
    asm volatile("mma.sync.aligned.m16n8k16.row.col.f32.f16.f16.f32 " \
        "{%0,%1,%2,%3}, {%4,%5,%6,%7}, {%8,%9}, {%0,%1,%2,%3};" \
        : "+f"((c)[0]), "+f"((c)[1]), "+f"((c)[2]), "+f"((c)[3]) \
        : "r"((a)[0]), "r"((a)[1]), "r"((a)[2]), "r"((a)[3]), "r"(b0), "r"(b1))

#define CP_ASYNC16(dst, src) \
    asm volatile("cp.async.ca.shared.global [%0], [%1], 16;" :: "r"(dst), "l"(src) : "memory")

// ---------------------------------------------------------------------------
// K1: softmax -> E = exp(softmax(scale * img@text^T))
// ---------------------------------------------------------------------------
__global__ void __launch_bounds__(256) k_softmax(
    const float* __restrict__ img, const float* __restrict__ tn,
    const float* __restrict__ ta, const float* __restrict__ ls)
{
    __shared__ float imgs[8][DIM];
    __shared__ float sims[8][192];
    const int b0 = blockIdx.x * 8;
    const int t = threadIdx.x;

    const float4* gi = (const float4*)(img + (size_t)b0 * DIM);
    float4* si = (float4*)&imgs[0][0];
    for (int i = t; i < 8 * (DIM / 4); i += 256) si[i] = gi[i];
    __syncthreads();

    const float scale = expf(ls[0]);

    if (t < 192) {
        const float* txt = (t < 96) ? (tn + (size_t)t * DIM) : (ta + (size_t)(t - 96) * DIM);
        const float4* tv = (const float4*)txt;
        float acc[8];
        #pragma unroll
        for (int bi = 0; bi < 8; bi++) acc[bi] = 0.f;
        for (int k = 0; k < DIM / 4; k++) {
            float4 x = tv[k];
            #pragma unroll
            for (int bi = 0; bi < 8; bi++) {
                float4 y = *(const float4*)&imgs[bi][k * 4];
                acc[bi] += x.x * y.x + x.y * y.y + x.z * y.z + x.w * y.w;
            }
        }
        #pragma unroll
        for (int bi = 0; bi < 8; bi++) sims[bi][t] = acc[bi] * scale;
    }
    __syncthreads();

    const int w = t >> 5, lane = t & 31;
    const int b = b0 + w;
    #pragma unroll
    for (int br = 0; br < 2; br++) {
        float v0 = sims[w][br * 96 + lane];
        float v1 = sims[w][br * 96 + lane + 32];
        float v2 = sims[w][br * 96 + lane + 64];
        float m = fmaxf(v0, fmaxf(v1, v2));
        #pragma unroll
        for (int off = 16; off > 0; off >>= 1)
            m = fmaxf(m, __shfl_xor_sync(0xffffffffu, m, off));
        float e0 = expf(v0 - m), e1 = expf(v1 - m), e2 = expf(v2 - m);
        float s = e0 + e1 + e2;
        #pragma unroll
        for (int off = 16; off > 0; off >>= 1)
            s += __shfl_xor_sync(0xffffffffu, s, off);
        float inv = 1.f / s;
        float* Eo = g_scratch + OFF_E + ((size_t)br * BATCH + b) * NN;
        Eo[lane]      = expf(e0 * inv);
        Eo[lane + 32] = expf(e1 * inv);
        Eo[lane + 64] = expf(e2 * inv);
    }
}

// ---------------------------------------------------------------------------
// K2: split-K fp32 GEMM with atomic accumulation.
// C[m][n] += A[m][k] @ Bm[k][n] over k in [z*KC, (z+1)*KC); bias added by z==0.
// A rows: row < 96 from A0, else A1 (when A1 != null); else all from A0.
// Targets must be pre-zeroed (k_prep).
// ---------------------------------------------------------------------------
__global__ void __launch_bounds__(256) k_gemm_sk(
    const float* __restrict__ A0, const float* __restrict__ A1,
    const float* __restrict__ Bm, const float* __restrict__ bias,
    int coff, int M, int N, int K, int KC)
{
    __shared__ float As[16][64];
    __shared__ float Bs[16][64];
    float* C = g_scratch + coff;
    const int n0 = blockIdx.x * 64, m0 = blockIdx.y * 64;
    const int z = blockIdx.z;
    const int t = threadIdx.x;
    const int tx = t & 15, ty = t >> 4;

    float acc[4][4];
    #pragma unroll
    for (int i = 0; i < 4; i++)
        #pragma unroll
        for (int j = 0; j < 4; j++) acc[i][j] = 0.f;

    const int kBeg = z * KC, kEnd = kBeg + KC;
    for (int k0 = kBeg; k0 < kEnd; k0 += 16) {
        __syncthreads();
        {
            int aRow = t >> 2, aCol = (t & 3) * 4;
            int row = m0 + aRow;
            float4 v = make_float4(0.f, 0.f, 0.f, 0.f);
            if (row < M) {
                const float* Ar = (A1 && row >= 96) ? (A1 + (size_t)(row - 96) * K)
                                                    : (A0 + (size_t)row * K);
                v = *(const float4*)&Ar[k0 + aCol];
            }
            As[aCol][aRow] = v.x; As[aCol + 1][aRow] = v.y;
            As[aCol + 2][aRow] = v.z; As[aCol + 3][aRow] = v.w;
            int bRow = t >> 4, bCol = (t & 15) * 4;
            float4 wv = *(const float4*)&Bm[(size_t)(k0 + bRow) * N + n0 + bCol];
            *(float4*)&Bs[bRow][bCol] = wv;
        }
        __syncthreads();
        #pragma unroll
        for (int kk = 0; kk < 16; kk++) {
            float4 a = *(const float4*)&As[kk][ty * 4];
            float4 bq = *(const float4*)&Bs[kk][tx * 4];
            float av[4] = {a.x, a.y, a.z, a.w};
            float bv[4] = {bq.x, bq.y, bq.z, bq.w};
            #pragma unroll
            for (int i = 0; i < 4; i++)
                #pragma unroll
                for (int j = 0; j < 4; j++) acc[i][j] += av[i] * bv[j];
        }
    }
    #pragma unroll
    for (int i = 0; i < 4; i++) {
        int m = m0 + ty * 4 + i;
        if (m < M) {
            #pragma unroll
            for (int j = 0; j < 4; j++) {
                int n = n0 + tx * 4 + j;
                float v = acc[i][j];
                if (z == 0 && bias) v += bias[n];
                atomicAdd(&C[(size_t)m * N + n], v);
            }
        }
    }
}

// ---------------------------------------------------------------------------
// K3: prep — zero PRE, T, S2; convert W2H[n][k] = fp16(W2[k][n])
// grid 2048 x 256 = 524288 threads
// ---------------------------------------------------------------------------
__global__ void __launch_bounds__(256) k_prep(const float* __restrict__ W2)
{
    int i = blockIdx.x * 256 + threadIdx.x;
    g_scratch[OFF_PRE + i] = 0.f;                 // 524288 = BATCH*DIM
    g_scratch[OFF_S2 + i] = 0.f;                  // 524288 = 2*BATCH*D2
    if (i < 2 * NN * DIM) g_scratch[OFF_T + i] = 0.f;
    if (i < DIM * D2) {
        int n = i >> 9, k = i & 511;
        __half* W2H = (__half*)(g_scratch + OFF_W2T);
        W2H[i] = __float2half(W2[(size_t)k * D2 + n]);
    }
}

// ---------------------------------------------------------------------------
// K4: fp16 mma.sync m16n8k16 kernel, double-buffered (cp.async B, reg-prefetch A).
// Block: 128 rows x 256 cols, K=512 in 32-wide chunks.
// 8 warps = 4(M) x 2(N); warp tile 32x128 = 2 mf x 16 nf.
// Each warp's 32 rows share one batch b -> shuffle row-reduce, atomicAdd to S2.
// ---------------------------------------------------------------------------
#define ASTR 40                       // half stride (80 B)
#define SMA (128 * ASTR * 2)          // bytes per A buffer (10240)
#define SMB (256 * ASTR * 2)          // bytes per B buffer (20480)
#define OFF_BS0 (2 * SMA)
#define OFF_B2S (2 * SMA + 2 * SMB)
#define SMEM_BYTES (OFF_B2S + 1024)

__global__ void __launch_bounds__(256, 1) k_mma(const float* __restrict__ b2)
{
    extern __shared__ __align__(16) char smem[];
    const uint32_t sb = smem_u32(smem);
    float* b2s = (float*)(smem + OFF_B2S);

    const int t = threadIdx.x, lane = t & 31, wid = t >> 5;
    const int warpM = wid & 3, warpN = wid >> 2;
    const int g = lane >> 2, tig = lane & 3;
    const int tile = blockIdx.x, beta = blockIdx.y;

    b2s[t] = b2[t];

    const int rowA = t >> 1, halfk = (t & 1) * 16;
    const int r = tile * 128 + rowA;
    const int bbA = r / 96, nidx = r - bbA * 96;
    const float ev = g_scratch[OFF_E + ((size_t)beta * BATCH + bbA) * NN + nidx];
    const float* pPre = g_scratch + OFF_PRE + (size_t)bbA * DIM + halfk;
    const float* pT   = g_scratch + OFF_T + ((size_t)beta * NN + nidx) * DIM + halfk;
    const __half* W2H = (const __half*)(g_scratch + OFF_W2T);
    const __half* pB  = W2H + (size_t)t * DIM;          // B row n = t
    const uint32_t aStAddr = sb + (uint32_t)(rowA * ASTR + halfk) * 2;
    const uint32_t bStAddr = sb + OFF_BS0 + (uint32_t)(t * ASTR) * 2;

    const uint32_t aLdBase = sb + (uint32_t)(((warpM * 32 + (lane & 15)) * ASTR
                              + ((lane >> 4) * 8)) * 2);
    const uint32_t bLdBase = sb + OFF_BS0 + (uint32_t)(((warpN * 128 + ((lane >> 4) * 8) + (lane & 7)) * ASTR
                              + (((lane >> 3) & 1) * 8)) * 2);

    float acc[2][16][4];
    #pragma unroll
    for (int mf = 0; mf < 2; mf++)
        #pragma unroll
        for (int nf = 0; nf < 16; nf++)
            #pragma unroll
            for (int q = 0; q < 4; q++) acc[mf][nf][q] = 0.f;

    // ---- prologue: fill chunk 0 into buffer 0
    {
        #pragma unroll
        for (int gi = 0; gi < 4; gi++)
            CP_ASYNC16(bStAddr + gi * 16, (const char*)(pB) + gi * 16);
        asm volatile("cp.async.commit_group;" ::: "memory");
        float4 pa0 = ((const float4*)pPre)[0], pa1 = ((const float4*)pPre)[1];
        float4 pa2 = ((const float4*)pPre)[2], pa3 = ((const float4*)pPre)[3];
        float4 ta0 = ((const float4*)pT)[0],  ta1 = ((const float4*)pT)[1];
        float4 ta2 = ((const float4*)pT)[2],  ta3 = ((const float4*)pT)[3];
        uint32_t u[8];
        u[0] = packh2(fmaxf(fmaf(ev, ta0.x, pa0.x), 0.f), fmaxf(fmaf(ev, ta0.y, pa0.y), 0.f));
        u[1] = packh2(fmaxf(fmaf(ev, ta0.z, pa0.z), 0.f), fmaxf(fmaf(ev, ta0.w, pa0.w), 0.f));
        u[2] = packh2(fmaxf(fmaf(ev, ta1.x, pa1.x), 0.f), fmaxf(fmaf(ev, ta1.y, pa1.y), 0.f));
        u[3] = packh2(fmaxf(fmaf(ev, ta1.z, pa1.z), 0.f), fmaxf(fmaf(ev, ta1.w, pa1.w), 0.f));
        u[4] = packh2(fmaxf(fmaf(ev, ta2.x, pa2.x), 0.f), fmaxf(fmaf(ev, ta2.y, pa2.y), 0.f));
        u[5] = packh2(fmaxf(fmaf(ev, ta2.z, pa2.z), 0.f), fmaxf(fmaf(ev, ta2.w, pa2.w), 0.f));
        u[6] = packh2(fmaxf(fmaf(ev, ta3.x, pa3.x), 0.f), fmaxf(fmaf(ev, ta3.y, pa3.y), 0.f));
        u[7] = packh2(fmaxf(fmaf(ev, ta3.z, pa3.z), 0.f), fmaxf(fmaf(ev, ta3.w, pa3.w), 0.f));
        asm volatile("st.shared.v4.b32 [%0], {%1,%2,%3,%4};"
                     :: "r"(aStAddr), "r"(u[0]), "r"(u[1]), "r"(u[2]), "r"(u[3]) : "memory");
        asm volatile("st.shared.v4.b32 [%0], {%1,%2,%3,%4};"
                     :: "r"(aStAddr + 16), "r"(u[4]), "r"(u[5]), "r"(u[6]), "r"(u[7]) : "memory");
        asm volatile("cp.async.wait_group 0;" ::: "memory");
    }
    __syncthreads();

    for (int c = 0; c < 16; c++) {
        const int p = c & 1, q = 1 - p;
        const bool nxt = (c + 1 < 16);
        float4 pa0, pa1, pa2, pa3, ta0, ta1, ta2, ta3;

        if (nxt) {
            const int k1 = (c + 1) * 32;
            #pragma unroll
            for (int gi = 0; gi < 4; gi++)
                CP_ASYNC16(bStAddr + q * SMB + gi * 16, (const char*)(pB + k1) + gi * 16);
            asm volatile("cp.async.commit_group;" ::: "memory");
            pa0 = ((const float4*)(pPre + k1))[0]; pa1 = ((const float4*)(pPre + k1))[1];
            pa2 = ((const float4*)(pPre + k1))[2]; pa3 = ((const float4*)(pPre + k1))[3];
            ta0 = ((const float4*)(pT + k1))[0];   ta1 = ((const float4*)(pT + k1))[1];
            ta2 = ((const float4*)(pT + k1))[2];   ta3 = ((const float4*)(pT + k1))[3];
        }

        const uint32_t aB = aLdBase + p * SMA;
        const uint32_t bB = bLdBase + p * SMB;
        #pragma unroll
        for (int ks = 0; ks < 2; ks++) {
            uint32_t af[2][4];
            #pragma unroll
            for (int mf = 0; mf < 2; mf++)
                LDSM_X4(af[mf][0], af[mf][1], af[mf][2], af[mf][3],
                        aB + (uint32_t)((mf * 16 * ASTR + ks * 16) * 2));
            #pragma unroll
            for (int nf2 = 0; nf2 < 8; nf2++) {
                uint32_t b0, b1, b2r, b3r;
                LDSM_X4(b0, b1, b2r, b3r,
                        bB + (uint32_t)((nf2 * 16 * ASTR + ks * 16) * 2));
                #pragma unroll
                for (int mf = 0; mf < 2; mf++) {
                    MMA_F16(acc[mf][2 * nf2],     af[mf], b0, b1);
                    MMA_F16(acc[mf][2 * nf2 + 1], af[mf], b2r, b3r);
                }
            }
        }

        if (nxt) {
            uint32_t u[8];
            u[0] = packh2(fmaxf(fmaf(ev, ta0.x, pa0.x), 0.f), fmaxf(fmaf(ev, ta0.y, pa0.y), 0.f));
            u[1] = packh2(fmaxf(fmaf(ev, ta0.z, pa0.z), 0.f), fmaxf(fmaf(ev, ta0.w, pa0.w), 0.f));
            u[2] = packh2(fmaxf(fmaf(ev, ta1.x, pa1.x), 0.f), fmaxf(fmaf(ev, ta1.y, pa1.y), 0.f));
            u[3] = packh2(fmaxf(fmaf(ev, ta1.z, pa1.z), 0.f), fmaxf(fmaf(ev, ta1.w, pa1.w), 0.f));
            u[4] = packh2(fmaxf(fmaf(ev, ta2.x, pa2.x), 0.f), fmaxf(fmaf(ev, ta2.y, pa2.y), 0.f));
            u[5] = packh2(fmaxf(fmaf(ev, ta2.z, pa2.z), 0.f), fmaxf(fmaf(ev, ta2.w, pa2.w), 0.f));
            u[6] = packh2(fmaxf(fmaf(ev, ta3.x, pa3.x), 0.f), fmaxf(fmaf(ev, ta3.y, pa3.y), 0.f));
            u[7] = packh2(fmaxf(fmaf(ev, ta3.z, pa3.z), 0.f), fmaxf(fmaf(ev, ta3.w, pa3.w), 0.f));
            const uint32_t ad = aStAddr + q * SMA;
            asm volatile("st.shared.v4.b32 [%0], {%1,%2,%3,%4};"
                         :: "r"(ad), "r"(u[0]), "r"(u[1]), "r"(u[2]), "r"(u[3]) : "memory");
            asm volatile("st.shared.v4.b32 [%0], {%1,%2,%3,%4};"
                         :: "r"(ad + 16), "r"(u[4]), "r"(u[5]), "r"(u[6]), "r"(u[7]) : "memory");
            asm volatile("cp.async.wait_group 0;" ::: "memory");
            __syncthreads();
        }
    }

    // Epilogue
    const int bw = (tile * 128 + warpM * 32) / 96;
    float* S2p = g_scratch + OFF_S2 + ((size_t)beta * BATCH + bw) * D2;
    #pragma unroll
    for (int nf = 0; nf < 16; nf++) {
        const int colE = warpN * 128 + nf * 8 + 2 * tig;
        const float be = b2s[colE], bo = b2s[colE + 1];
        float ve = 0.f, vo = 0.f;
        #pragma unroll
        for (int mf = 0; mf < 2; mf++) {
            ve += fmaxf(acc[mf][nf][0] + be, 0.f) + fmaxf(acc[mf][nf][2] + be, 0.f);
            vo += fmaxf(acc[mf][nf][1] + bo, 0.f) + fmaxf(acc[mf][nf][3] + bo, 0.f);
        }
        #pragma unroll
        for (int m = 4; m <= 16; m <<= 1) {
            ve += __shfl_xor_sync(0xffffffffu, ve, m);
            vo += __shfl_xor_sync(0xffffffffu, vo, m);
        }
        if (g == 0) {
            atomicAdd(S2p + colE, ve);
            atomicAdd(S2p + colE + 1, vo);
        }
    }
}

// ---------------------------------------------------------------------------
// K5: out = (S2/96) @ W3 + b3
// ---------------------------------------------------------------------------
__global__ void __launch_bounds__(128) k_final(
    const float* __restrict__ W3, const float* __restrict__ b3,
    float* __restrict__ out)
{
    __shared__ float s2s[8][D2];
    const int r0 = blockIdx.x * 8;
    const float* S2 = g_scratch + OFF_S2 + (size_t)r0 * D2;
    for (int i = threadIdx.x; i < 8 * D2; i += 128)
        s2s[i >> 8][i & 255] = S2[i];
    __syncthreads();
    const int c2 = threadIdx.x;
    float acc[8];
    #pragma unroll
    for (int p = 0; p < 8; p++) acc[p] = 0.f;
    for (int cc = 0; cc < D2; cc++) {
        float w3 = W3[(size_t)cc * D4 + c2];
        #pragma unroll
        for (int p = 0; p < 8; p++) acc[p] += s2s[p][cc] * w3;
    }
    const float bb = b3[c2];
    #pragma unroll
    for (int p = 0; p < 8; p++)
        out[(size_t)(r0 + p) * D4 + c2] = acc[p] * (1.f / 96.f) + bb;
}

// ---------------------------------------------------------------------------
extern "C" void kernel_launch(void* const* d_in, const int* in_sizes, int n_in,
                              void* d_out, int out_size)
{
    const float* img = (const float*)d_in[0];
    const float* tn  = (const float*)d_in[1];
    const float* ta  = (const float*)d_in[2];
    const float* ls  = (const float*)d_in[3];
    const float* W1  = (const float*)d_in[4];
    const float* b1  = (const float*)d_in[5];
    const float* W2  = (const float*)d_in[6];
    const float* b2  = (const float*)d_in[7];
    const float* W3  = (const float*)d_in[8];
    const float* b3  = (const float*)d_in[9];
    float* out = (float*)d_out;

    cudaFuncSetAttribute(k_mma, cudaFuncAttributeMaxDynamicSharedMemorySize, SMEM_BYTES);

    // zero atomic targets + convert W2 first (single stream serializes deps)
    k_prep<<<2048, 256>>>(W2);
    k_softmax<<<BATCH / 8, 256>>>(img, tn, ta, ls);
    // Pre = img @ W1[:512,:] + b1   (split-K 4)
    k_gemm_sk<<<dim3(DIM / 64, BATCH / 64, 4), 256>>>(
        img, nullptr, W1, b1, OFF_PRE, BATCH, DIM, DIM, DIM / 4);
    // T = [tn; ta] @ W1[512:,:]     (both branches in one launch, split-K 4)
    k_gemm_sk<<<dim3(DIM / 64, 3, 4), 256>>>(
        tn, ta, W1 + DIM * DIM, nullptr, OFF_T, 2 * NN, DIM, DIM, DIM / 4);
    // fused layer-1 construction + layer-2 GEMM + relu + sum over n
    k_mma<<<dim3(98304 / 128, 2), 256, SMEM_BYTES>>>(b2);
    // layer 3 on the n-averaged representation
    k_final<<<(2 * BATCH) / 8, 128>>>(W3, b3, out);
}

// round 17
// speedup vs baseline: 1.5067x; 1.5067x over previous
#include <cuda_runtime.h>
#include <cuda_fp16.h>
#include <cstdint>

// Problem constants
#define BATCH 1024
#define NN 96
#define DIM 512
#define D2 256
#define D4 128

// Scratch layout (floats; W2H region reinterpreted as half)
#define OFF_PRE 0                        // [1024][512]  img@W1_top + b1
#define OFF_T   (OFF_PRE + BATCH*DIM)    // [2][96][512] text@W1_bot
#define OFF_E   (OFF_T + 2*NN*DIM)       // [2][1024][96] exp(softmax(sims))
#define OFF_S2  (OFF_E + 2*BATCH*NN)     // [2][1024][256] sum_n relu(h1@W2+b2)
#define OFF_W2T (OFF_S2 + 2*BATCH*D2)    // half[256][512] = fp16(W2^T)
#define SCRATCH_TOTAL (OFF_W2T + DIM*D2)

__device__ float g_scratch[SCRATCH_TOTAL];

__device__ __forceinline__ uint32_t smem_u32(const void* p) {
    uint32_t a;
    asm("{ .reg .u64 t; cvta.to.shared.u64 t, %1; cvt.u32.u64 %0, t; }"
        : "=r"(a) : "l"(p));
    return a;
}
__device__ __forceinline__ uint32_t packh2(float x, float y) {
    __half2 h = __floats2half2_rn(x, y);
    return *(uint32_t*)&h;
}

#define LDSM_X4(r0, r1, r2, r3, addr) \
    asm volatile("ldmatrix.sync.aligned.m8n8.x4.shared.b16 {%0,%1,%2,%3}, [%4];" \
        : "=r"(r0), "=r"(r1), "=r"(r2), "=r"(r3) : "r"(addr))

#define MMA_F16(c, a, b0, b1) \
    asm volatile("mma.sync.aligned.m16n8k16.row.col.f32.f16.f16.f32 " \
        "{%0,%1,%2,%3}, {%4,%5,%6,%7}, {%8,%9}, {%0,%1,%2,%3};" \
        : "+f"((c)[0]), "+f"((c)[1]), "+f"((c)[2]), "+f"((c)[3]) \
        : "r"((a)[0]), "r"((a)[1]), "r"((a)[2]), "r"((a)[3]), "r"(b0), "r"(b1))

#define CP_ASYNC16(dst, src) \
    asm volatile("cp.async.ca.shared.global [%0], [%1], 16;" :: "r"(dst), "l"(src) : "memory")

// ---------------------------------------------------------------------------
// K1: softmax -> E = exp(softmax(scale * img@text^T))
// ---------------------------------------------------------------------------
__global__ void __launch_bounds__(256) k_softmax(
    const float* __restrict__ img, const float* __restrict__ tn,
    const float* __restrict__ ta, const float* __restrict__ ls)
{
    __shared__ float imgs[8][DIM];
    __shared__ float sims[8][192];
    const int b0 = blockIdx.x * 8;
    const int t = threadIdx.x;

    const float4* gi = (const float4*)(img + (size_t)b0 * DIM);
    float4* si = (float4*)&imgs[0][0];
    for (int i = t; i < 8 * (DIM / 4); i += 256) si[i] = gi[i];
    __syncthreads();

    const float scale = expf(ls[0]);

    if (t < 192) {
        const float* txt = (t < 96) ? (tn + (size_t)t * DIM) : (ta + (size_t)(t - 96) * DIM);
        const float4* tv = (const float4*)txt;
        float acc[8];
        #pragma unroll
        for (int bi = 0; bi < 8; bi++) acc[bi] = 0.f;
        for (int k = 0; k < DIM / 4; k++) {
            float4 x = tv[k];
            #pragma unroll
            for (int bi = 0; bi < 8; bi++) {
                float4 y = *(const float4*)&imgs[bi][k * 4];
                acc[bi] += x.x * y.x + x.y * y.y + x.z * y.z + x.w * y.w;
            }
        }
        #pragma unroll
        for (int bi = 0; bi < 8; bi++) sims[bi][t] = acc[bi] * scale;
    }
    __syncthreads();

    const int w = t >> 5, lane = t & 31;
    const int b = b0 + w;
    #pragma unroll
    for (int br = 0; br < 2; br++) {
        float v0 = sims[w][br * 96 + lane];
        float v1 = sims[w][br * 96 + lane + 32];
        float v2 = sims[w][br * 96 + lane + 64];
        float m = fmaxf(v0, fmaxf(v1, v2));
        #pragma unroll
        for (int off = 16; off > 0; off >>= 1)
            m = fmaxf(m, __shfl_xor_sync(0xffffffffu, m, off));
        float e0 = expf(v0 - m), e1 = expf(v1 - m), e2 = expf(v2 - m);
        float s = e0 + e1 + e2;
        #pragma unroll
        for (int off = 16; off > 0; off >>= 1)
            s += __shfl_xor_sync(0xffffffffu, s, off);
        float inv = 1.f / s;
        float* Eo = g_scratch + OFF_E + ((size_t)br * BATCH + b) * NN;
        Eo[lane]      = expf(e0 * inv);
        Eo[lane + 32] = expf(e1 * inv);
        Eo[lane + 64] = expf(e2 * inv);
    }
}

// ---------------------------------------------------------------------------
// K2a: direct-store fp32 GEMM (Pre).  C = A@Bm + bias, 64x64 tile, BK=16.
// ---------------------------------------------------------------------------
__global__ void __launch_bounds__(256) k_gemm(
    const float* __restrict__ A, const float* __restrict__ Bm,
    const float* __restrict__ bias, int coff, int M, int N, int K)
{
    __shared__ float As[16][64];
    __shared__ float Bs[16][64];
    float* C = g_scratch + coff;
    const int n0 = blockIdx.x * 64, m0 = blockIdx.y * 64;
    const int t = threadIdx.x;
    const int tx = t & 15, ty = t >> 4;

    float acc[4][4];
    #pragma unroll
    for (int i = 0; i < 4; i++)
        #pragma unroll
        for (int j = 0; j < 4; j++) acc[i][j] = 0.f;

    for (int k0 = 0; k0 < K; k0 += 16) {
        __syncthreads();
        {
            int aRow = t >> 2, aCol = (t & 3) * 4;
            float4 v = make_float4(0.f, 0.f, 0.f, 0.f);
            if (m0 + aRow < M)
                v = *(const float4*)&A[(size_t)(m0 + aRow) * K + k0 + aCol];
            As[aCol][aRow] = v.x; As[aCol + 1][aRow] = v.y;
            As[aCol + 2][aRow] = v.z; As[aCol + 3][aRow] = v.w;
            int bRow = t >> 4, bCol = (t & 15) * 4;
            float4 wv = *(const float4*)&Bm[(size_t)(k0 + bRow) * N + n0 + bCol];
            *(float4*)&Bs[bRow][bCol] = wv;
        }
        __syncthreads();
        #pragma unroll
        for (int kk = 0; kk < 16; kk++) {
            float4 a = *(const float4*)&As[kk][ty * 4];
            float4 bq = *(const float4*)&Bs[kk][tx * 4];
            float av[4] = {a.x, a.y, a.z, a.w};
            float bv[4] = {bq.x, bq.y, bq.z, bq.w};
            #pragma unroll
            for (int i = 0; i < 4; i++)
                #pragma unroll
                for (int j = 0; j < 4; j++) acc[i][j] += av[i] * bv[j];
        }
    }
    #pragma unroll
    for (int i = 0; i < 4; i++) {
        int m = m0 + ty * 4 + i;
        if (m < M) {
            #pragma unroll
            for (int j = 0; j < 4; j++) {
                int n = n0 + tx * 4 + j;
                float bb = bias ? bias[n] : 0.f;
                C[(size_t)m * N + n] = acc[i][j] + bb;
            }
        }
    }
}

// ---------------------------------------------------------------------------
// K2b: split-K fp32 GEMM with atomic accumulation (text T only; target
// pre-zeroed by k_prep). A rows < 96 from A0, else A1.
// ---------------------------------------------------------------------------
__global__ void __launch_bounds__(256) k_gemm_sk(
    const float* __restrict__ A0, const float* __restrict__ A1,
    const float* __restrict__ Bm, int coff, int M, int N, int K, int KC)
{
    __shared__ float As[16][64];
    __shared__ float Bs[16][64];
    float* C = g_scratch + coff;
    const int n0 = blockIdx.x * 64, m0 = blockIdx.y * 64;
    const int z = blockIdx.z;
    const int t = threadIdx.x;
    const int tx = t & 15, ty = t >> 4;

    float acc[4][4];
    #pragma unroll
    for (int i = 0; i < 4; i++)
        #pragma unroll
        for (int j = 0; j < 4; j++) acc[i][j] = 0.f;

    const int kBeg = z * KC, kEnd = kBeg + KC;
    for (int k0 = kBeg; k0 < kEnd; k0 += 16) {
        __syncthreads();
        {
            int aRow = t >> 2, aCol = (t & 3) * 4;
            int row = m0 + aRow;
            float4 v = make_float4(0.f, 0.f, 0.f, 0.f);
            if (row < M) {
                const float* Ar = (row >= 96) ? (A1 + (size_t)(row - 96) * K)
                                              : (A0 + (size_t)row * K);
                v = *(const float4*)&Ar[k0 + aCol];
            }
            As[aCol][aRow] = v.x; As[aCol + 1][aRow] = v.y;
            As[aCol + 2][aRow] = v.z; As[aCol + 3][aRow] = v.w;
            int bRow = t >> 4, bCol = (t & 15) * 4;
            float4 wv = *(const float4*)&Bm[(size_t)(k0 + bRow) * N + n0 + bCol];
            *(float4*)&Bs[bRow][bCol] = wv;
        }
        __syncthreads();
        #pragma unroll
        for (int kk = 0; kk < 16; kk++) {
            float4 a = *(const float4*)&As[kk][ty * 4];
            float4 bq = *(const float4*)&Bs[kk][tx * 4];
            float av[4] = {a.x, a.y, a.z, a.w};
            float bv[4] = {bq.x, bq.y, bq.z, bq.w};
            #pragma unroll
            for (int i = 0; i < 4; i++)
                #pragma unroll
                for (int j = 0; j < 4; j++) acc[i][j] += av[i] * bv[j];
        }
    }
    #pragma unroll
    for (int i = 0; i < 4; i++) {
        int m = m0 + ty * 4 + i;
        if (m < M) {
            #pragma unroll
            for (int j = 0; j < 4; j++) {
                int n = n0 + tx * 4 + j;
                atomicAdd(&C[(size_t)m * N + n], acc[i][j]);
            }
        }
    }
}

// ---------------------------------------------------------------------------
// K3: prep — zero S2 + T; convert W2H[n][k] = fp16(W2[k][n])
// grid 2048 x 256
// ---------------------------------------------------------------------------
__global__ void __launch_bounds__(256) k_prep(const float* __restrict__ W2)
{
    int i = blockIdx.x * 256 + threadIdx.x;
    g_scratch[OFF_S2 + i] = 0.f;                  // 524288 = 2*BATCH*D2
    if (i < 2 * NN * DIM) g_scratch[OFF_T + i] = 0.f;
    if (i < DIM * D2) {
        int n = i >> 9, k = i & 511;
        __half* W2H = (__half*)(g_scratch + OFF_W2T);
        W2H[i] = __float2half(W2[(size_t)k * D2 + n]);
    }
}

// ---------------------------------------------------------------------------
// K4: fp16 mma.sync m16n8k16 kernel, double-buffered (cp.async B, reg-prefetch A).
// Identical to the 416us R8 version.
// ---------------------------------------------------------------------------
#define ASTR 40                       // half stride (80 B)
#define SMA (128 * ASTR * 2)          // bytes per A buffer (10240)
#define SMB (256 * ASTR * 2)          // bytes per B buffer (20480)
#define OFF_BS0 (2 * SMA)
#define OFF_B2S (2 * SMA + 2 * SMB)
#define SMEM_BYTES (OFF_B2S + 1024)

__global__ void __launch_bounds__(256, 1) k_mma(const float* __restrict__ b2)
{
    extern __shared__ __align__(16) char smem[];
    const uint32_t sb = smem_u32(smem);
    float* b2s = (float*)(smem + OFF_B2S);

    const int t = threadIdx.x, lane = t & 31, wid = t >> 5;
    const int warpM = wid & 3, warpN = wid >> 2;
    const int g = lane >> 2, tig = lane & 3;
    const int tile = blockIdx.x, beta = blockIdx.y;

    b2s[t] = b2[t];

    const int rowA = t >> 1, halfk = (t & 1) * 16;
    const int r = tile * 128 + rowA;
    const int bbA = r / 96, nidx = r - bbA * 96;
    const float ev = g_scratch[OFF_E + ((size_t)beta * BATCH + bbA) * NN + nidx];
    const float* pPre = g_scratch + OFF_PRE + (size_t)bbA * DIM + halfk;
    const float* pT   = g_scratch + OFF_T + ((size_t)beta * NN + nidx) * DIM + halfk;
    const __half* W2H = (const __half*)(g_scratch + OFF_W2T);
    const __half* pB  = W2H + (size_t)t * DIM;          // B row n = t
    const uint32_t aStAddr = sb + (uint32_t)(rowA * ASTR + halfk) * 2;
    const uint32_t bStAddr = sb + OFF_BS0 + (uint32_t)(t * ASTR) * 2;

    const uint32_t aLdBase = sb + (uint32_t)(((warpM * 32 + (lane & 15)) * ASTR
                              + ((lane >> 4) * 8)) * 2);
    const uint32_t bLdBase = sb + OFF_BS0 + (uint32_t)(((warpN * 128 + ((lane >> 4) * 8) + (lane & 7)) * ASTR
                              + (((lane >> 3) & 1) * 8)) * 2);

    float acc[2][16][4];
    #pragma unroll
    for (int mf = 0; mf < 2; mf++)
        #pragma unroll
        for (int nf = 0; nf < 16; nf++)
            #pragma unroll
            for (int q = 0; q < 4; q++) acc[mf][nf][q] = 0.f;

    // ---- prologue: fill chunk 0 into buffer 0
    {
        #pragma unroll
        for (int gi = 0; gi < 4; gi++)
            CP_ASYNC16(bStAddr + gi * 16, (const char*)(pB) + gi * 16);
        asm volatile("cp.async.commit_group;" ::: "memory");
        float4 pa0 = ((const float4*)pPre)[0], pa1 = ((const float4*)pPre)[1];
        float4 pa2 = ((const float4*)pPre)[2], pa3 = ((const float4*)pPre)[3];
        float4 ta0 = ((const float4*)pT)[0],  ta1 = ((const float4*)pT)[1];
        float4 ta2 = ((const float4*)pT)[2],  ta3 = ((const float4*)pT)[3];
        uint32_t u[8];
        u[0] = packh2(fmaxf(fmaf(ev, ta0.x, pa0.x), 0.f), fmaxf(fmaf(ev, ta0.y, pa0.y), 0.f));
        u[1] = packh2(fmaxf(fmaf(ev, ta0.z, pa0.z), 0.f), fmaxf(fmaf(ev, ta0.w, pa0.w), 0.f));
        u[2] = packh2(fmaxf(fmaf(ev, ta1.x, pa1.x), 0.f), fmaxf(fmaf(ev, ta1.y, pa1.y), 0.f));
        u[3] = packh2(fmaxf(fmaf(ev, ta1.z, pa1.z), 0.f), fmaxf(fmaf(ev, ta1.w, pa1.w), 0.f));
        u[4] = packh2(fmaxf(fmaf(ev, ta2.x, pa2.x), 0.f), fmaxf(fmaf(ev, ta2.y, pa2.y), 0.f));
        u[5] = packh2(fmaxf(fmaf(ev, ta2.z, pa2.z), 0.f), fmaxf(fmaf(ev, ta2.w, pa2.w), 0.f));
        u[6] = packh2(fmaxf(fmaf(ev, ta3.x, pa3.x), 0.f), fmaxf(fmaf(ev, ta3.y, pa3.y), 0.f));
        u[7] = packh2(fmaxf(fmaf(ev, ta3.z, pa3.z), 0.f), fmaxf(fmaf(ev, ta3.w, pa3.w), 0.f));
        asm volatile("st.shared.v4.b32 [%0], {%1,%2,%3,%4};"
                     :: "r"(aStAddr), "r"(u[0]), "r"(u[1]), "r"(u[2]), "r"(u[3]) : "memory");
        asm volatile("st.shared.v4.b32 [%0], {%1,%2,%3,%4};"
                     :: "r"(aStAddr + 16), "r"(u[4]), "r"(u[5]), "r"(u[6]), "r"(u[7]) : "memory");
        asm volatile("cp.async.wait_group 0;" ::: "memory");
    }
    __syncthreads();

    for (int c = 0; c < 16; c++) {
        const int p = c & 1, q = 1 - p;
        const bool nxt = (c + 1 < 16);
        float4 pa0, pa1, pa2, pa3, ta0, ta1, ta2, ta3;

        if (nxt) {
            const int k1 = (c + 1) * 32;
            #pragma unroll
            for (int gi = 0; gi < 4; gi++)
                CP_ASYNC16(bStAddr + q * SMB + gi * 16, (const char*)(pB + k1) + gi * 16);
            asm volatile("cp.async.commit_group;" ::: "memory");
            pa0 = ((const float4*)(pPre + k1))[0]; pa1 = ((const float4*)(pPre + k1))[1];
            pa2 = ((const float4*)(pPre + k1))[2]; pa3 = ((const float4*)(pPre + k1))[3];
            ta0 = ((const float4*)(pT + k1))[0];   ta1 = ((const float4*)(pT + k1))[1];
            ta2 = ((const float4*)(pT + k1))[2];   ta3 = ((const float4*)(pT + k1))[3];
        }

        const uint32_t aB = aLdBase + p * SMA;
        const uint32_t bB = bLdBase + p * SMB;
        #pragma unroll
        for (int ks = 0; ks < 2; ks++) {
            uint32_t af[2][4];
            #pragma unroll
            for (int mf = 0; mf < 2; mf++)
                LDSM_X4(af[mf][0], af[mf][1], af[mf][2], af[mf][3],
                        aB + (uint32_t)((mf * 16 * ASTR + ks * 16) * 2));
            #pragma unroll
            for (int nf2 = 0; nf2 < 8; nf2++) {
                uint32_t b0, b1, b2r, b3r;
                LDSM_X4(b0, b1, b2r, b3r,
                        bB + (uint32_t)((nf2 * 16 * ASTR + ks * 16) * 2));
                #pragma unroll
                for (int mf = 0; mf < 2; mf++) {
                    MMA_F16(acc[mf][2 * nf2],     af[mf], b0, b1);
                    MMA_F16(acc[mf][2 * nf2 + 1], af[mf], b2r, b3r);
                }
            }
        }

        if (nxt) {
            uint32_t u[8];
            u[0] = packh2(fmaxf(fmaf(ev, ta0.x, pa0.x), 0.f), fmaxf(fmaf(ev, ta0.y, pa0.y), 0.f));
            u[1] = packh2(fmaxf(fmaf(ev, ta0.z, pa0.z), 0.f), fmaxf(fmaf(ev, ta0.w, pa0.w), 0.f));
            u[2] = packh2(fmaxf(fmaf(ev, ta1.x, pa1.x), 0.f), fmaxf(fmaf(ev, ta1.y, pa1.y), 0.f));
            u[3] = packh2(fmaxf(fmaf(ev, ta1.z, pa1.z), 0.f), fmaxf(fmaf(ev, ta1.w, pa1.w), 0.f));
            u[4] = packh2(fmaxf(fmaf(ev, ta2.x, pa2.x), 0.f), fmaxf(fmaf(ev, ta2.y, pa2.y), 0.f));
            u[5] = packh2(fmaxf(fmaf(ev, ta2.z, pa2.z), 0.f), fmaxf(fmaf(ev, ta2.w, pa2.w), 0.f));
            u[6] = packh2(fmaxf(fmaf(ev, ta3.x, pa3.x), 0.f), fmaxf(fmaf(ev, ta3.y, pa3.y), 0.f));
            u[7] = packh2(fmaxf(fmaf(ev, ta3.z, pa3.z), 0.f), fmaxf(fmaf(ev, ta3.w, pa3.w), 0.f));
            const uint32_t ad = aStAddr + q * SMA;
            asm volatile("st.shared.v4.b32 [%0], {%1,%2,%3,%4};"
                         :: "r"(ad), "r"(u[0]), "r"(u[1]), "r"(u[2]), "r"(u[3]) : "memory");
            asm volatile("st.shared.v4.b32 [%0], {%1,%2,%3,%4};"
                         :: "r"(ad + 16), "r"(u[4]), "r"(u[5]), "r"(u[6]), "r"(u[7]) : "memory");
            asm volatile("cp.async.wait_group 0;" ::: "memory");
            __syncthreads();
        }
    }

    // Epilogue
    const int bw = (tile * 128 + warpM * 32) / 96;
    float* S2p = g_scratch + OFF_S2 + ((size_t)beta * BATCH + bw) * D2;
    #pragma unroll
    for (int nf = 0; nf < 16; nf++) {
        const int colE = warpN * 128 + nf * 8 + 2 * tig;
        const float be = b2s[colE], bo = b2s[colE + 1];
        float ve = 0.f, vo = 0.f;
        #pragma unroll
        for (int mf = 0; mf < 2; mf++) {
            ve += fmaxf(acc[mf][nf][0] + be, 0.f) + fmaxf(acc[mf][nf][2] + be, 0.f);
            vo += fmaxf(acc[mf][nf][1] + bo, 0.f) + fmaxf(acc[mf][nf][3] + bo, 0.f);
        }
        #pragma unroll
        for (int m = 4; m <= 16; m <<= 1) {
            ve += __shfl_xor_sync(0xffffffffu, ve, m);
            vo += __shfl_xor_sync(0xffffffffu, vo, m);
        }
        if (g == 0) {
            atomicAdd(S2p + colE, ve);
            atomicAdd(S2p + colE + 1, vo);
        }
    }
}

// ---------------------------------------------------------------------------
// K5: out = (S2/96) @ W3 + b3
// ---------------------------------------------------------------------------
__global__ void __launch_bounds__(128) k_final(
    const float* __restrict__ W3, const float* __restrict__ b3,
    float* __restrict__ out)
{
    __shared__ float s2s[8][D2];
    const int r0 = blockIdx.x * 8;
    const float* S2 = g_scratch + OFF_S2 + (size_t)r0 * D2;
    for (int i = threadIdx.x; i < 8 * D2; i += 128)
        s2s[i >> 8][i & 255] = S2[i];
    __syncthreads();
    const int c2 = threadIdx.x;
    float acc[8];
    #pragma unroll
    for (int p = 0; p < 8; p++) acc[p] = 0.f;
    for (int cc = 0; cc < D2; cc++) {
        float w3 = W3[(size_t)cc * D4 + c2];
        #pragma unroll
        for (int p = 0; p < 8; p++) acc[p] += s2s[p][cc] * w3;
    }
    const float bb = b3[c2];
    #pragma unroll
    for (int p = 0; p < 8; p++)
        out[(size_t)(r0 + p) * D4 + c2] = acc[p] * (1.f / 96.f) + bb;
}

// ---------------------------------------------------------------------------
extern "C" void kernel_launch(void* const* d_in, const int* in_sizes, int n_in,
                              void* d_out, int out_size)
{
    const float* img = (const float*)d_in[0];
    const float* tn  = (const float*)d_in[1];
    const float* ta  = (const float*)d_in[2];
    const float* ls  = (const float*)d_in[3];
    const float* W1  = (const float*)d_in[4];
    const float* b1  = (const float*)d_in[5];
    const float* W2  = (const float*)d_in[6];
    const float* b2  = (const float*)d_in[7];
    const float* W3  = (const float*)d_in[8];
    const float* b3  = (const float*)d_in[9];
    float* out = (float*)d_out;

    cudaFuncSetAttribute(k_mma, cudaFuncAttributeMaxDynamicSharedMemorySize, SMEM_BYTES);

    // zero T + S2, convert W2 (runs first; single stream serializes deps)
    k_prep<<<2048, 256>>>(W2);
    k_softmax<<<BATCH / 8, 256>>>(img, tn, ta, ls);
    // Pre = img @ W1[:512,:] + b1   (direct store, as in the 416us version)
    k_gemm<<<dim3(DIM / 64, BATCH / 64), 256>>>(img, W1, b1, OFF_PRE, BATCH, DIM, DIM);
    // T = [tn; ta] @ W1[512:,:]     (fused branches, split-K 4, atomic into zeroed T)
    k_gemm_sk<<<dim3(DIM / 64, 3, 4), 256>>>(
        tn, ta, W1 + DIM * DIM, OFF_T, 2 * NN, DIM, DIM, DIM / 4);
    // fused layer-1 construction + layer-2 GEMM + relu + sum over n
    k_mma<<<dim3(98304 / 128, 2), 256, SMEM_BYTES>>>(b2);
    // layer 3 on the n-averaged representation
    k_final<<<(2 * BATCH) / 8, 128>>>(W3, b3, out);
}